// round 2
// baseline (speedup 1.0000x reference)
#include <cuda_runtime.h>
#include <math.h>

#define Bq 4
#define Cc 32
#define Hh 128
#define Ww 128
#define HW (Hh*Ww)
#define NKK 9
#define NHEADS 4
#define MSIZE 512
#define HD 8

// scratch (no allocs allowed)
__device__ float g_x3[Bq*Cc*HW];
__device__ float g_yavg[Bq*Cc];
__device__ float g_ysp[Bq*Cc];
__device__ float g_ych[Bq*Cc];

// ---------------- kernel 1: per-(b,c) spatial mean ----------------
__global__ void k_avg(const float* __restrict__ x) {
    int bc = blockIdx.x;
    const float* p = x + bc * HW;
    float s = 0.f;
    for (int i = threadIdx.x; i < HW; i += 256) s += p[i];
    __shared__ float red[256];
    red[threadIdx.x] = s; __syncthreads();
    for (int st = 128; st > 0; st >>= 1) {
        if (threadIdx.x < st) red[threadIdx.x] += red[threadIdx.x + st];
        __syncthreads();
    }
    if (threadIdx.x == 0) g_yavg[bc] = red[0] * (1.0f / (float)HW);
}

// ---------------- kernel 2: tiny squeeze MLPs ----------------
__global__ void k_mlp(const float* __restrict__ fs_w1, const float* __restrict__ fs_w2,
                      const float* __restrict__ fc_w1, const float* __restrict__ fc_w2) {
    __shared__ float ys[Bq*Cc];
    int t = threadIdx.x;           // 128 threads, t = b*32+c
    ys[t] = g_yavg[t];
    __syncthreads();
    int b = t >> 5, c = t & 31;
    const float* yb = ys + b * 32;
    // spatial branch: hidden = 2
    float hs0 = 0.f, hs1 = 0.f;
    #pragma unroll
    for (int j = 0; j < 32; j++) { hs0 += yb[j] * fs_w1[j]; hs1 += yb[j] * fs_w1[32 + j]; }
    hs0 = fmaxf(hs0, 0.f); hs1 = fmaxf(hs1, 0.f);
    float sp = hs0 * fs_w2[c*2 + 0] + hs1 * fs_w2[c*2 + 1];
    g_ysp[t] = 1.f / (1.f + __expf(-sp));
    // channel branch: hidden = 4
    float ch = 0.f;
    #pragma unroll
    for (int r = 0; r < 4; r++) {
        float a = 0.f;
        #pragma unroll
        for (int j = 0; j < 32; j++) a += yb[j] * fc_w1[r*32 + j];
        ch += fmaxf(a, 0.f) * fc_w2[c*4 + r];
    }
    g_ych[t] = 1.f / (1.f + __expf(-ch));
}

// ---------------- kernel 3: fused offset-conv + DCNv2 ----------------
__global__ __launch_bounds__(256) void k_dcn(
    const float* __restrict__ x,
    const float* __restrict__ off_w, const float* __restrict__ off_b,
    const float* __restrict__ dcn_w, const float* __restrict__ dcn_b)
{
    __shared__ __align__(16) float wbuf[32*32*9];   // 36KB, phased: off_w (7776) then dcn_w (9216)
    __shared__ float bbuf[32];
    int tid = threadIdx.x;

    // phase 1 weights: off_w (27,32,3,3) flattened
    for (int i = tid; i < 27*32*9; i += 256) wbuf[i] = off_w[i];
    if (tid < 27) bbuf[tid] = off_b[tid];
    __syncthreads();

    int p = blockIdx.x * 256 + tid;
    int b = p >> 14;
    int rem = p & 16383;
    int y = rem >> 7, x0i = rem & 127;
    const float* xb = x + ((long)b << 19);   // b*32*16384

    // offset conv: om[27]
    float om[27];
    #pragma unroll
    for (int j = 0; j < 27; j++) om[j] = bbuf[j];
    for (int ky = 0; ky < 3; ky++) {
        int yy = y + ky - 1;
        if (yy < 0 || yy > 127) continue;
        for (int kx = 0; kx < 3; kx++) {
            int xx = x0i + kx - 1;
            if (xx < 0 || xx > 127) continue;
            int kidx = ky*3 + kx;
            const float* xp = xb + yy*128 + xx;
            const float* wk = wbuf + kidx;
            for (int c = 0; c < 32; c++) {
                float v = xp[c << 14];
                const float* ws = wk + c*9;
                #pragma unroll
                for (int j = 0; j < 27; j++) om[j] += v * ws[j*288];
            }
        }
    }
    __syncthreads();

    // phase 2 weights: dcn_w (32,32,3,3) -> w[o][c][k] at o*288 + c*9 + k
    for (int i = tid; i < 32*32*9; i += 256) wbuf[i] = dcn_w[i];
    if (tid < 32) bbuf[tid] = dcn_b[tid];
    __syncthreads();

    float acc[32];
    #pragma unroll
    for (int o = 0; o < 32; o++) acc[o] = bbuf[o];

    for (int k = 0; k < 9; k++) {
        float ofy = om[2*k], ofx = om[2*k + 1];
        float msk = 1.f / (1.f + __expf(-om[18 + k]));
        float py = (float)y   + (float)(k / 3 - 1) + ofy;
        float px = (float)x0i + (float)(k % 3 - 1) + ofx;
        // safety clamp: does not change results (all corners already invalid out here)
        py = fminf(fmaxf(py, -4.0f), 131.0f);
        px = fminf(fmaxf(px, -4.0f), 131.0f);
        float fy = floorf(py), fx = floorf(px);
        float wy = py - fy, wx = px - fx;
        int iy0 = (int)fy, ix0 = (int)fx;
        int iy1 = iy0 + 1, ix1 = ix0 + 1;
        float vy0 = (iy0 >= 0 && iy0 <= 127) ? 1.f : 0.f;
        float vy1 = (iy1 >= 0 && iy1 <= 127) ? 1.f : 0.f;
        float vx0 = (ix0 >= 0 && ix0 <= 127) ? 1.f : 0.f;
        float vx1 = (ix1 >= 0 && ix1 <= 127) ? 1.f : 0.f;
        float w00 = (1.f - wy) * (1.f - wx) * vy0 * vx0 * msk;
        float w01 = (1.f - wy) * wx         * vy0 * vx1 * msk;
        float w10 = wy         * (1.f - wx) * vy1 * vx0 * msk;
        float w11 = wy         * wx         * vy1 * vx1 * msk;
        int cy0 = min(max(iy0, 0), 127), cy1 = min(max(iy1, 0), 127);
        int cx0 = min(max(ix0, 0), 127), cx1 = min(max(ix1, 0), 127);
        int a00 = cy0*128 + cx0, a01 = cy0*128 + cx1;
        int a10 = cy1*128 + cx0, a11 = cy1*128 + cx1;
        const float* wk = wbuf + k;
        for (int c = 0; c < 32; c++) {
            const float* xp = xb + (c << 14);
            float val = w00 * xp[a00] + w01 * xp[a01] + w10 * xp[a10] + w11 * xp[a11];
            const float* ws = wk + c*9;
            #pragma unroll
            for (int o = 0; o < 32; o++) acc[o] += val * ws[o*288];
        }
    }
    float* x3p = g_x3 + ((long)b << 19) + y*128 + x0i;
    #pragma unroll
    for (int o = 0; o < 32; o++) x3p[o << 14] = acc[o];
}

// ---------------- kernel 4: fused switch-conv + gate + memory attention ----------------
__global__ __launch_bounds__(256) void k_final(
    const float* __restrict__ x,
    const float* __restrict__ sw_w1, const float* __restrict__ sw_b1,
    const float* __restrict__ sw_w2, const float* __restrict__ sw_b2,
    const float* __restrict__ mem, float* __restrict__ out)
{
    // mems is read via float4 (LDS.128): MUST be 16B aligned within the
    // shared segment (R1 failure: offset was ≡8 mod 16 -> misaligned address).
    __shared__ __align__(16) float mems[MSIZE*HD];  // 16KB, one head at a time
    __shared__ __align__(16) float w1s[32*64];      // 8KB
    __shared__ float w2s[64];
    __shared__ float ysps[Bq*Cc], ychs[Bq*Cc];
    __shared__ float b1s[32];
    __shared__ float b2s[2];

    int tid = threadIdx.x;
    for (int i = tid; i < 2048; i += 256) w1s[i] = sw_w1[i];
    if (tid < 64)  w2s[tid] = sw_w2[tid];
    if (tid < 128) { ysps[tid] = g_ysp[tid]; ychs[tid] = g_ych[tid]; }
    if (tid < 32)  b1s[tid] = sw_b1[tid];
    if (tid < 2)   b2s[tid] = sw_b2[tid];
    __syncthreads();

    int p = blockIdx.x * 256 + tid;
    int b = p >> 14, sp = p & 16383;
    const float* xb  = x    + ((long)b << 19) + sp;
    const float* x3b = g_x3 + ((long)b << 19) + sp;

    float xr[32];   // x, later xo, later output
    float h1[32];
    #pragma unroll
    for (int o = 0; o < 32; o++) h1[o] = b1s[o];
    #pragma unroll
    for (int c = 0; c < 32; c++) {
        float v = xb[c << 14];
        xr[c] = v;
        #pragma unroll
        for (int o = 0; o < 32; o++) h1[o] += v * w1s[o*64 + c];
    }
    #pragma unroll
    for (int c = 0; c < 32; c++) {
        float v = x3b[c << 14];
        #pragma unroll
        for (int o = 0; o < 32; o++) h1[o] += v * w1s[o*64 + 32 + c];
    }
    float s0 = b2s[0], s1 = b2s[1];
    #pragma unroll
    for (int o = 0; o < 32; o++) {
        float h = fmaxf(h1[o], 0.f);
        s0 += h * w2s[o];
        s1 += h * w2s[32 + o];
    }
    s0 = 1.f / (1.f + __expf(-s0));
    s1 = 1.f / (1.f + __expf(-s1));
    const float* yspb = ysps + b*32;
    const float* ychb = ychs + b*32;
    #pragma unroll
    for (int c = 0; c < 32; c++) xr[c] = xr[c] + yspb[c]*s0 + ychb[c]*s1;  // xo

    // memory attention, one head per phase. Scores are small (|s| << 10):
    // exp(s) without max-subtraction is numerically safe and mathematically
    // identical to softmax after the final 1/l normalization.
    const float rs = 0.3535533905932738f;  // 1/sqrt(HD)
    for (int hd = 0; hd < 4; hd++) {
        __syncthreads();
        for (int i = tid; i < MSIZE*HD; i += 256) mems[i] = mem[hd*MSIZE*HD + i];
        __syncthreads();
        float q[8];
        #pragma unroll
        for (int d = 0; d < 8; d++) q[d] = xr[hd*8 + d] * rs;
        float l = 0.f;
        float r[8];
        #pragma unroll
        for (int d = 0; d < 8; d++) r[d] = 0.f;
        const float4* mp = (const float4*)mems;  // broadcast reads: all lanes same addr
        #pragma unroll 4
        for (int m = 0; m < MSIZE; m++) {
            float4 a = mp[2*m], c4 = mp[2*m + 1];
            float s = q[0]*a.x + q[1]*a.y + q[2]*a.z + q[3]*a.w
                    + q[4]*c4.x + q[5]*c4.y + q[6]*c4.z + q[7]*c4.w;
            float e = __expf(s);
            l += e;
            r[0] += e*a.x;  r[1] += e*a.y;  r[2] += e*a.z;  r[3] += e*a.w;
            r[4] += e*c4.x; r[5] += e*c4.y; r[6] += e*c4.z; r[7] += e*c4.w;
        }
        float inv = 1.f / l;
        #pragma unroll
        for (int d = 0; d < 8; d++) xr[hd*8 + d] += r[d] * inv;
    }

    float* op = out + ((long)b << 19) + sp;
    #pragma unroll
    for (int c = 0; c < 32; c++) op[c << 14] = xr[c];
}

extern "C" void kernel_launch(void* const* d_in, const int* in_sizes, int n_in,
                              void* d_out, int out_size) {
    const float* x     = (const float*)d_in[0];
    const float* fs_w1 = (const float*)d_in[1];
    const float* fs_w2 = (const float*)d_in[2];
    const float* fc_w1 = (const float*)d_in[3];
    const float* fc_w2 = (const float*)d_in[4];
    const float* sw_w1 = (const float*)d_in[5];
    const float* sw_b1 = (const float*)d_in[6];
    const float* sw_w2 = (const float*)d_in[7];
    const float* sw_b2 = (const float*)d_in[8];
    const float* off_w = (const float*)d_in[9];
    const float* off_b = (const float*)d_in[10];
    const float* dcn_w = (const float*)d_in[11];
    const float* dcn_b = (const float*)d_in[12];
    const float* mem   = (const float*)d_in[13];
    float* out = (float*)d_out;

    k_avg<<<Bq*Cc, 256>>>(x);
    k_mlp<<<1, 128>>>(fs_w1, fs_w2, fc_w1, fc_w2);
    k_dcn<<<(Bq*HW)/256, 256>>>(x, off_w, off_b, dcn_w, dcn_b);
    k_final<<<(Bq*HW)/256, 256>>>(x, sw_w1, sw_b1, sw_w2, sw_b2, mem, out);
}

// round 3
// speedup vs baseline: 2.2005x; 2.2005x over previous
#include <cuda_runtime.h>
#include <math.h>

#define Bq 4
#define Cc 32
#define Hh 128
#define Ww 128
#define HW (Hh*Ww)
#define MSIZE 512
#define HD 8

typedef unsigned long long ull;

__device__ __forceinline__ ull pk2(float lo, float hi) {
    ull r; asm("mov.b64 %0,{%1,%2};" : "=l"(r) : "f"(lo), "f"(hi)); return r;
}
__device__ __forceinline__ void upk2(float& lo, float& hi, ull v) {
    asm("mov.b64 {%0,%1},%2;" : "=f"(lo), "=f"(hi) : "l"(v));
}
__device__ __forceinline__ void fma2(ull& d, ull a, ull b, ull c) {
    asm("fma.rn.f32x2 %0,%1,%2,%3;" : "=l"(d) : "l"(a), "l"(b), "l"(c));
}
__device__ __forceinline__ void mul2(ull& d, ull a, ull b) {
    asm("mul.rn.f32x2 %0,%1,%2;" : "=l"(d) : "l"(a), "l"(b));
}

// scratch (no allocs allowed)
__device__ float g_x3[Bq*Cc*HW];
__device__ float g_yavg[Bq*Cc];
__device__ float g_ysp[Bq*Cc];
__device__ float g_ych[Bq*Cc];

// ---------------- kernel 1: per-(b,c) spatial mean ----------------
__global__ void k_avg(const float* __restrict__ x) {
    int bc = blockIdx.x;
    const float* p = x + bc * HW;
    float s = 0.f;
    for (int i = threadIdx.x; i < HW; i += 256) s += p[i];
    __shared__ float red[256];
    red[threadIdx.x] = s; __syncthreads();
    for (int st = 128; st > 0; st >>= 1) {
        if (threadIdx.x < st) red[threadIdx.x] += red[threadIdx.x + st];
        __syncthreads();
    }
    if (threadIdx.x == 0) g_yavg[bc] = red[0] * (1.0f / (float)HW);
}

// ---------------- kernel 2: tiny squeeze MLPs ----------------
__global__ void k_mlp(const float* __restrict__ fs_w1, const float* __restrict__ fs_w2,
                      const float* __restrict__ fc_w1, const float* __restrict__ fc_w2) {
    __shared__ float ys[Bq*Cc];
    int t = threadIdx.x;           // 128 threads, t = b*32+c
    ys[t] = g_yavg[t];
    __syncthreads();
    int b = t >> 5, c = t & 31;
    const float* yb = ys + b * 32;
    float hs0 = 0.f, hs1 = 0.f;
    #pragma unroll
    for (int j = 0; j < 32; j++) { hs0 += yb[j] * fs_w1[j]; hs1 += yb[j] * fs_w1[32 + j]; }
    hs0 = fmaxf(hs0, 0.f); hs1 = fmaxf(hs1, 0.f);
    float sp = hs0 * fs_w2[c*2 + 0] + hs1 * fs_w2[c*2 + 1];
    g_ysp[t] = 1.f / (1.f + __expf(-sp));
    float ch = 0.f;
    #pragma unroll
    for (int r = 0; r < 4; r++) {
        float a = 0.f;
        #pragma unroll
        for (int j = 0; j < 32; j++) a += yb[j] * fc_w1[r*32 + j];
        ch += fmaxf(a, 0.f) * fc_w2[c*4 + r];
    }
    g_ych[t] = 1.f / (1.f + __expf(-ch));
}

// ---------------- kernel 3: fused offset-conv + DCNv2 ----------------
// Weights transposed in smem so the inner o/j loops read contiguous floats
// via LDS.128 (ulonglong2) and accumulate with packed fma.rn.f32x2.
__global__ __launch_bounds__(256) void k_dcn(
    const float* __restrict__ x,
    const float* __restrict__ off_w, const float* __restrict__ off_b,
    const float* __restrict__ dcn_w, const float* __restrict__ dcn_b)
{
    // phase1: woff[k][c][j28]  (9*32*28 = 8064 floats)
    // phase2: wdcn[k][c][o32]  (9*32*32 = 9216 floats)  -- 36KB
    __shared__ __align__(16) float wbuf[9216];
    __shared__ float bbuf[32];
    int tid = threadIdx.x;

    // phase 1: off_w (27,32,9) elem (j,c,k) at j*288+c*9+k -> wbuf[(k*32+c)*28+j]
    for (int i = tid; i < 7776; i += 256) {
        int j = i / 288, r = i - j*288, c = r / 9, k = r - c*9;
        wbuf[(k*32 + c)*28 + j] = off_w[i];
    }
    for (int i = tid; i < 288; i += 256) wbuf[i*28 + 27] = 0.f;  // pad lane
    if (tid < 27) bbuf[tid] = off_b[tid];
    if (tid >= 27 && tid < 28) bbuf[tid] = 0.f;
    __syncthreads();

    int p = blockIdx.x * 256 + tid;
    int b = p >> 14;
    int rem = p & 16383;
    int y = rem >> 7, x0i = rem & 127;
    const float* xb = x + ((long)b << 19);   // b*32*16384

    ull om2[14];
    #pragma unroll
    for (int j = 0; j < 14; j++) om2[j] = pk2(bbuf[2*j], bbuf[2*j+1]);

    for (int ky = 0; ky < 3; ky++) {
        int yy = y + ky - 1;
        if (yy < 0 || yy > 127) continue;
        for (int kx = 0; kx < 3; kx++) {
            int xx = x0i + kx - 1;
            if (xx < 0 || xx > 127) continue;
            int kidx = ky*3 + kx;
            const float* xp = xb + yy*128 + xx;
            for (int c = 0; c < 32; c++) {
                float v = xp[c << 14];
                ull v2 = pk2(v, v);
                const ulonglong2* wp = (const ulonglong2*)(wbuf + (kidx*32 + c)*28);
                #pragma unroll
                for (int i = 0; i < 7; i++) {
                    ulonglong2 u = wp[i];
                    fma2(om2[2*i],   v2, u.x, om2[2*i]);
                    fma2(om2[2*i+1], v2, u.y, om2[2*i+1]);
                }
            }
        }
    }
    float om[28];
    #pragma unroll
    for (int j = 0; j < 14; j++) upk2(om[2*j], om[2*j+1], om2[j]);
    __syncthreads();

    // phase 2: dcn_w (32,32,9) elem (o,c,k) at o*288+c*9+k -> wbuf[(k*32+c)*32+o]
    for (int i = tid; i < 9216; i += 256) {
        int o = i / 288, r = i - o*288, c = r / 9, k = r - c*9;
        wbuf[(k*32 + c)*32 + o] = dcn_w[i];
    }
    if (tid < 32) bbuf[tid] = dcn_b[tid];
    __syncthreads();

    ull acc2[16];
    #pragma unroll
    for (int i = 0; i < 16; i++) acc2[i] = pk2(bbuf[2*i], bbuf[2*i+1]);

    for (int k = 0; k < 9; k++) {
        float ofy = om[2*k], ofx = om[2*k + 1];
        float msk = 1.f / (1.f + __expf(-om[18 + k]));
        float py = (float)y   + (float)(k / 3 - 1) + ofy;
        float px = (float)x0i + (float)(k % 3 - 1) + ofx;
        py = fminf(fmaxf(py, -4.0f), 131.0f);
        px = fminf(fmaxf(px, -4.0f), 131.0f);
        float fy = floorf(py), fx = floorf(px);
        float wy = py - fy, wx = px - fx;
        int iy0 = (int)fy, ix0 = (int)fx;
        int iy1 = iy0 + 1, ix1 = ix0 + 1;
        float vy0 = (iy0 >= 0 && iy0 <= 127) ? 1.f : 0.f;
        float vy1 = (iy1 >= 0 && iy1 <= 127) ? 1.f : 0.f;
        float vx0 = (ix0 >= 0 && ix0 <= 127) ? 1.f : 0.f;
        float vx1 = (ix1 >= 0 && ix1 <= 127) ? 1.f : 0.f;
        float w00 = (1.f - wy) * (1.f - wx) * vy0 * vx0 * msk;
        float w01 = (1.f - wy) * wx         * vy0 * vx1 * msk;
        float w10 = wy         * (1.f - wx) * vy1 * vx0 * msk;
        float w11 = wy         * wx         * vy1 * vx1 * msk;
        int cy0 = min(max(iy0, 0), 127), cy1 = min(max(iy1, 0), 127);
        int cx0 = min(max(ix0, 0), 127), cx1 = min(max(ix1, 0), 127);
        int a00 = cy0*128 + cx0, a01 = cy0*128 + cx1;
        int a10 = cy1*128 + cx0, a11 = cy1*128 + cx1;
        for (int c = 0; c < 32; c++) {
            const float* xp = xb + (c << 14);
            float val = w00 * xp[a00] + w01 * xp[a01] + w10 * xp[a10] + w11 * xp[a11];
            ull v2 = pk2(val, val);
            const ulonglong2* wp = (const ulonglong2*)(wbuf + (k*32 + c)*32);
            #pragma unroll
            for (int i = 0; i < 8; i++) {
                ulonglong2 u = wp[i];
                fma2(acc2[2*i],   v2, u.x, acc2[2*i]);
                fma2(acc2[2*i+1], v2, u.y, acc2[2*i+1]);
            }
        }
    }
    float* x3p = g_x3 + ((long)b << 19) + y*128 + x0i;
    #pragma unroll
    for (int i = 0; i < 16; i++) {
        float a, bfl; upk2(a, bfl, acc2[i]);
        x3p[(2*i) << 14]   = a;
        x3p[(2*i+1) << 14] = bfl;
    }
}

// ---------------- kernel 4: fused switch-conv + gate + memory attention ----------------
__global__ __launch_bounds__(256) void k_final(
    const float* __restrict__ x,
    const float* __restrict__ sw_w1, const float* __restrict__ sw_b1,
    const float* __restrict__ sw_w2, const float* __restrict__ sw_b2,
    const float* __restrict__ mem, float* __restrict__ out)
{
    __shared__ __align__(16) float mems[MSIZE*HD];   // 16KB, one head per phase
    __shared__ __align__(16) float w1t[64*32];       // transposed: w1t[c][o]
    __shared__ __align__(16) ull   w2p[32];          // (w2[0][o], w2[1][o]) pairs
    __shared__ float ysps[Bq*Cc], ychs[Bq*Cc];
    __shared__ float b1s[32];
    __shared__ float b2s[2];

    int tid = threadIdx.x;
    for (int i = tid; i < 2048; i += 256) {
        int o = i >> 6, c = i & 63;                  // sw_w1[o*64+c]
        w1t[c*32 + o] = sw_w1[i];
    }
    if (tid < 32)  w2p[tid] = pk2(sw_w2[tid], sw_w2[32 + tid]);
    if (tid < 128) { ysps[tid] = g_ysp[tid]; ychs[tid] = g_ych[tid]; }
    if (tid < 32)  b1s[tid] = sw_b1[tid];
    if (tid < 2)   b2s[tid] = sw_b2[tid];
    __syncthreads();

    int p = blockIdx.x * 256 + tid;
    int b = p >> 14, sp = p & 16383;
    const float* xb  = x    + ((long)b << 19) + sp;
    const float* x3b = g_x3 + ((long)b << 19) + sp;

    float xr[32];
    ull h2[16];
    #pragma unroll
    for (int i = 0; i < 16; i++) h2[i] = pk2(b1s[2*i], b1s[2*i+1]);
    #pragma unroll
    for (int c = 0; c < 32; c++) {
        float v = xb[c << 14];
        xr[c] = v;
        ull v2 = pk2(v, v);
        const ulonglong2* wp = (const ulonglong2*)(w1t + c*32);
        #pragma unroll
        for (int i = 0; i < 8; i++) {
            ulonglong2 u = wp[i];
            fma2(h2[2*i],   v2, u.x, h2[2*i]);
            fma2(h2[2*i+1], v2, u.y, h2[2*i+1]);
        }
    }
    #pragma unroll
    for (int c = 0; c < 32; c++) {
        float v = x3b[c << 14];
        ull v2 = pk2(v, v);
        const ulonglong2* wp = (const ulonglong2*)(w1t + (32 + c)*32);
        #pragma unroll
        for (int i = 0; i < 8; i++) {
            ulonglong2 u = wp[i];
            fma2(h2[2*i],   v2, u.x, h2[2*i]);
            fma2(h2[2*i+1], v2, u.y, h2[2*i+1]);
        }
    }
    ull s01 = pk2(b2s[0], b2s[1]);
    #pragma unroll
    for (int i = 0; i < 16; i++) {
        float ha, hb; upk2(ha, hb, h2[i]);
        ha = fmaxf(ha, 0.f); hb = fmaxf(hb, 0.f);
        fma2(s01, pk2(ha, ha), w2p[2*i],   s01);
        fma2(s01, pk2(hb, hb), w2p[2*i+1], s01);
    }
    float s0, s1; upk2(s0, s1, s01);
    s0 = 1.f / (1.f + __expf(-s0));
    s1 = 1.f / (1.f + __expf(-s1));
    const float* yspb = ysps + b*32;
    const float* ychb = ychs + b*32;
    #pragma unroll
    for (int c = 0; c < 32; c++) xr[c] = xr[c] + yspb[c]*s0 + ychb[c]*s1;  // xo

    // memory attention; scores are small -> one-pass exp without max-sub.
    const float rs = 0.3535533905932738f;  // 1/sqrt(HD)
    for (int hd = 0; hd < 4; hd++) {
        __syncthreads();
        for (int i = tid; i < MSIZE*HD; i += 256) mems[i] = mem[hd*MSIZE*HD + i];
        __syncthreads();
        ull q2[4], r2[4];
        #pragma unroll
        for (int d = 0; d < 4; d++) {
            q2[d] = pk2(xr[hd*8 + 2*d] * rs, xr[hd*8 + 2*d + 1] * rs);
            r2[d] = 0ULL;
        }
        float l = 0.f;
        const ulonglong2* mp = (const ulonglong2*)mems;  // broadcast LDS.128
        #pragma unroll 4
        for (int m = 0; m < MSIZE; m++) {
            ulonglong2 u0 = mp[2*m], u1 = mp[2*m + 1];
            ull s2;
            mul2(s2, q2[0], u0.x);
            fma2(s2, q2[1], u0.y, s2);
            fma2(s2, q2[2], u1.x, s2);
            fma2(s2, q2[3], u1.y, s2);
            float slo, shi; upk2(slo, shi, s2);
            float e = __expf(slo + shi);
            l += e;
            ull e2 = pk2(e, e);
            fma2(r2[0], e2, u0.x, r2[0]);
            fma2(r2[1], e2, u0.y, r2[1]);
            fma2(r2[2], e2, u1.x, r2[2]);
            fma2(r2[3], e2, u1.y, r2[3]);
        }
        float inv = 1.f / l;
        #pragma unroll
        for (int d = 0; d < 4; d++) {
            float ra, rb; upk2(ra, rb, r2[d]);
            xr[hd*8 + 2*d]     += ra * inv;
            xr[hd*8 + 2*d + 1] += rb * inv;
        }
    }

    float* op = out + ((long)b << 19) + sp;
    #pragma unroll
    for (int c = 0; c < 32; c++) op[c << 14] = xr[c];
}

extern "C" void kernel_launch(void* const* d_in, const int* in_sizes, int n_in,
                              void* d_out, int out_size) {
    const float* x     = (const float*)d_in[0];
    const float* fs_w1 = (const float*)d_in[1];
    const float* fs_w2 = (const float*)d_in[2];
    const float* fc_w1 = (const float*)d_in[3];
    const float* fc_w2 = (const float*)d_in[4];
    const float* sw_w1 = (const float*)d_in[5];
    const float* sw_b1 = (const float*)d_in[6];
    const float* sw_w2 = (const float*)d_in[7];
    const float* sw_b2 = (const float*)d_in[8];
    const float* off_w = (const float*)d_in[9];
    const float* off_b = (const float*)d_in[10];
    const float* dcn_w = (const float*)d_in[11];
    const float* dcn_b = (const float*)d_in[12];
    const float* mem   = (const float*)d_in[13];
    float* out = (float*)d_out;

    k_avg<<<Bq*Cc, 256>>>(x);
    k_mlp<<<1, 128>>>(fs_w1, fs_w2, fc_w1, fc_w2);
    k_dcn<<<(Bq*HW)/256, 256>>>(x, off_w, off_b, dcn_w, dcn_b);
    k_final<<<(Bq*HW)/256, 256>>>(x, sw_w1, sw_b1, sw_w2, sw_b2, mem, out);
}

// round 4
// speedup vs baseline: 2.4120x; 1.0961x over previous
#include <cuda_runtime.h>
#include <math.h>

#define Bq 4
#define Cc 32
#define Hh 128
#define Ww 128
#define HW (Hh*Ww)
#define BHW (Bq*HW)
#define MSIZE 512
#define HD 8

typedef unsigned long long ull;

__device__ __forceinline__ ull pk2(float lo, float hi) {
    ull r; asm("mov.b64 %0,{%1,%2};" : "=l"(r) : "f"(lo), "f"(hi)); return r;
}
__device__ __forceinline__ void upk2(float& lo, float& hi, ull v) {
    asm("mov.b64 {%0,%1},%2;" : "=f"(lo), "=f"(hi) : "l"(v));
}
__device__ __forceinline__ void fma2(ull& d, ull a, ull b, ull c) {
    asm("fma.rn.f32x2 %0,%1,%2,%3;" : "=l"(d) : "l"(a), "l"(b), "l"(c));
}
__device__ __forceinline__ void mul2(ull& d, ull a, ull b) {
    asm("mul.rn.f32x2 %0,%1,%2;" : "=l"(d) : "l"(a), "l"(b));
}
__device__ __forceinline__ void add2(ull& d, ull a, ull b) {
    asm("add.rn.f32x2 %0,%1,%2;" : "=l"(d) : "l"(a), "l"(b));
}
__device__ __forceinline__ float ex2f(float x) {
    float r; asm("ex2.approx.f32 %0,%1;" : "=f"(r) : "f"(x)); return r;
}

// scratch (no allocs allowed)
__device__ float g_x3[Bq*Cc*HW];
__device__ float g_om[27*BHW];     // offset-conv output, [j][p]
__device__ float g_yavg[Bq*Cc];
__device__ float g_ysp[Bq*Cc];
__device__ float g_ych[Bq*Cc];

// ---------------- kernel 1: per-(b,c) spatial mean ----------------
__global__ void k_avg(const float* __restrict__ x) {
    int bc = blockIdx.x;
    const float* p = x + bc * HW;
    float s = 0.f;
    for (int i = threadIdx.x; i < HW; i += 256) s += p[i];
    __shared__ float red[256];
    red[threadIdx.x] = s; __syncthreads();
    for (int st = 128; st > 0; st >>= 1) {
        if (threadIdx.x < st) red[threadIdx.x] += red[threadIdx.x + st];
        __syncthreads();
    }
    if (threadIdx.x == 0) g_yavg[bc] = red[0] * (1.0f / (float)HW);
}

// ---------------- kernel 2: tiny squeeze MLPs ----------------
__global__ void k_mlp(const float* __restrict__ fs_w1, const float* __restrict__ fs_w2,
                      const float* __restrict__ fc_w1, const float* __restrict__ fc_w2) {
    __shared__ float ys[Bq*Cc];
    int t = threadIdx.x;           // 128 threads, t = b*32+c
    ys[t] = g_yavg[t];
    __syncthreads();
    int b = t >> 5, c = t & 31;
    const float* yb = ys + b * 32;
    float hs0 = 0.f, hs1 = 0.f;
    #pragma unroll
    for (int j = 0; j < 32; j++) { hs0 += yb[j] * fs_w1[j]; hs1 += yb[j] * fs_w1[32 + j]; }
    hs0 = fmaxf(hs0, 0.f); hs1 = fmaxf(hs1, 0.f);
    float sp = hs0 * fs_w2[c*2 + 0] + hs1 * fs_w2[c*2 + 1];
    g_ysp[t] = 1.f / (1.f + __expf(-sp));
    float ch = 0.f;
    #pragma unroll
    for (int r = 0; r < 4; r++) {
        float a = 0.f;
        #pragma unroll
        for (int j = 0; j < 32; j++) a += yb[j] * fc_w1[r*32 + j];
        ch += fmaxf(a, 0.f) * fc_w2[c*4 + r];
    }
    g_ych[t] = 1.f / (1.f + __expf(-ch));
}

// ---------------- kernel 3a: offset conv (3x3, 32->27) ----------------
__global__ __launch_bounds__(256) void k_off(
    const float* __restrict__ x,
    const float* __restrict__ off_w, const float* __restrict__ off_b)
{
    __shared__ __align__(16) float wbuf[9*32*28];   // woff[k][c][j28]
    __shared__ float bbuf[28];
    int tid = threadIdx.x;
    // off_w (27,32,9): elem (j,c,k) at j*288+c*9+k -> wbuf[(k*32+c)*28+j]
    for (int i = tid; i < 7776; i += 256) {
        int j = i / 288, r = i - j*288, c = r / 9, k = r - c*9;
        wbuf[(k*32 + c)*28 + j] = off_w[i];
    }
    for (int i = tid; i < 288; i += 256) wbuf[i*28 + 27] = 0.f;
    if (tid < 27) bbuf[tid] = off_b[tid];
    if (tid == 27) bbuf[27] = 0.f;
    __syncthreads();

    int p = blockIdx.x * 256 + tid;
    int b = p >> 14;
    int rem = p & 16383;
    int y = rem >> 7, x0i = rem & 127;
    const float* xb = x + ((long)b << 19);

    ull om2[14];
    #pragma unroll
    for (int j = 0; j < 14; j++) om2[j] = pk2(bbuf[2*j], bbuf[2*j+1]);

    for (int ky = 0; ky < 3; ky++) {
        int yy = y + ky - 1;
        if (yy < 0 || yy > 127) continue;
        for (int kx = 0; kx < 3; kx++) {
            int xx = x0i + kx - 1;
            if (xx < 0 || xx > 127) continue;
            int kidx = ky*3 + kx;
            const float* xp = xb + yy*128 + xx;
            for (int c = 0; c < 32; c++) {
                float v = xp[c << 14];
                ull v2 = pk2(v, v);
                const ulonglong2* wp = (const ulonglong2*)(wbuf + (kidx*32 + c)*28);
                #pragma unroll
                for (int i = 0; i < 7; i++) {
                    ulonglong2 u = wp[i];
                    fma2(om2[2*i],   v2, u.x, om2[2*i]);
                    fma2(om2[2*i+1], v2, u.y, om2[2*i+1]);
                }
            }
        }
    }
    #pragma unroll
    for (int j = 0; j < 13; j++) {
        float a, bb; upk2(a, bb, om2[j]);
        g_om[(2*j)*BHW + p]   = a;
        g_om[(2*j+1)*BHW + p] = bb;
    }
    { float a, bb; upk2(a, bb, om2[13]); g_om[26*BHW + p] = a; }
}

// ---------------- kernel 3b: deformable gather + 3x3 conv ----------------
__global__ __launch_bounds__(256) void k_dcn2(
    const float* __restrict__ x,
    const float* __restrict__ dcn_w, const float* __restrict__ dcn_b)
{
    __shared__ __align__(16) float wbuf[9216];   // wdcn[k][c][o32], 36KB
    __shared__ float bbuf[32];
    int tid = threadIdx.x;
    // dcn_w (32,32,9) elem (o,c,k) at o*288+c*9+k -> wbuf[(k*32+c)*32+o]
    for (int i = tid; i < 9216; i += 256) {
        int o = i / 288, r = i - o*288, c = r / 9, k = r - c*9;
        wbuf[(k*32 + c)*32 + o] = dcn_w[i];
    }
    if (tid < 32) bbuf[tid] = dcn_b[tid];
    __syncthreads();

    int p = blockIdx.x * 256 + tid;
    int b = p >> 14;
    int rem = p & 16383;
    int y = rem >> 7, x0i = rem & 127;
    const float* xb = x + ((long)b << 19);

    ull acc2[16];
    #pragma unroll
    for (int i = 0; i < 16; i++) acc2[i] = pk2(bbuf[2*i], bbuf[2*i+1]);

    for (int k = 0; k < 9; k++) {
        float ofy = g_om[(2*k)*BHW + p];
        float ofx = g_om[(2*k+1)*BHW + p];
        float msk = 1.f / (1.f + __expf(-g_om[(18+k)*BHW + p]));
        float py = (float)y   + (float)(k / 3 - 1) + ofy;
        float px = (float)x0i + (float)(k % 3 - 1) + ofx;
        py = fminf(fmaxf(py, -4.0f), 131.0f);
        px = fminf(fmaxf(px, -4.0f), 131.0f);
        float fy = floorf(py), fx = floorf(px);
        float wy = py - fy, wx = px - fx;
        int iy0 = (int)fy, ix0 = (int)fx;
        int iy1 = iy0 + 1, ix1 = ix0 + 1;
        float vy0 = (iy0 >= 0 && iy0 <= 127) ? 1.f : 0.f;
        float vy1 = (iy1 >= 0 && iy1 <= 127) ? 1.f : 0.f;
        float vx0 = (ix0 >= 0 && ix0 <= 127) ? 1.f : 0.f;
        float vx1 = (ix1 >= 0 && ix1 <= 127) ? 1.f : 0.f;
        float w00 = (1.f - wy) * (1.f - wx) * vy0 * vx0 * msk;
        float w01 = (1.f - wy) * wx         * vy0 * vx1 * msk;
        float w10 = wy         * (1.f - wx) * vy1 * vx0 * msk;
        float w11 = wy         * wx         * vy1 * vx1 * msk;
        int cy0 = min(max(iy0, 0), 127), cy1 = min(max(iy1, 0), 127);
        int cx0 = min(max(ix0, 0), 127), cx1 = min(max(ix1, 0), 127);
        int a00 = cy0*128 + cx0, a01 = cy0*128 + cx1;
        int a10 = cy1*128 + cx0, a11 = cy1*128 + cx1;
        for (int c = 0; c < 32; c++) {
            const float* xp = xb + (c << 14);
            float val = w00 * xp[a00] + w01 * xp[a01] + w10 * xp[a10] + w11 * xp[a11];
            ull v2 = pk2(val, val);
            const ulonglong2* wp = (const ulonglong2*)(wbuf + (k*32 + c)*32);
            #pragma unroll
            for (int i = 0; i < 8; i++) {
                ulonglong2 u = wp[i];
                fma2(acc2[2*i],   v2, u.x, acc2[2*i]);
                fma2(acc2[2*i+1], v2, u.y, acc2[2*i+1]);
            }
        }
    }
    float* x3p = g_x3 + ((long)b << 19) + y*128 + x0i;
    #pragma unroll
    for (int i = 0; i < 16; i++) {
        float a, bfl; upk2(a, bfl, acc2[i]);
        x3p[(2*i) << 14]   = a;
        x3p[(2*i+1) << 14] = bfl;
    }
}

// ---------------- kernel 4: switch-conv + gates -> xo (writes out) ----------------
__global__ __launch_bounds__(256) void k_conv(
    const float* __restrict__ x,
    const float* __restrict__ sw_w1, const float* __restrict__ sw_b1,
    const float* __restrict__ sw_w2, const float* __restrict__ sw_b2,
    float* __restrict__ out)
{
    __shared__ __align__(16) float w1t[64*32];       // transposed: w1t[c][o]
    __shared__ __align__(16) ull   w2p[32];
    __shared__ float ysps[Bq*Cc], ychs[Bq*Cc];
    __shared__ float b1s[32];
    __shared__ float b2s[2];

    int tid = threadIdx.x;
    for (int i = tid; i < 2048; i += 256) {
        int o = i >> 6, c = i & 63;
        w1t[c*32 + o] = sw_w1[i];
    }
    if (tid < 32)  w2p[tid] = pk2(sw_w2[tid], sw_w2[32 + tid]);
    if (tid < 128) { ysps[tid] = g_ysp[tid]; ychs[tid] = g_ych[tid]; }
    if (tid < 32)  b1s[tid] = sw_b1[tid];
    if (tid < 2)   b2s[tid] = sw_b2[tid];
    __syncthreads();

    int p = blockIdx.x * 256 + tid;
    int b = p >> 14, sp = p & 16383;
    const float* xb  = x    + ((long)b << 19) + sp;
    const float* x3b = g_x3 + ((long)b << 19) + sp;

    float xr[32];
    ull h2[16];
    #pragma unroll
    for (int i = 0; i < 16; i++) h2[i] = pk2(b1s[2*i], b1s[2*i+1]);
    #pragma unroll
    for (int c = 0; c < 32; c++) {
        float v = xb[c << 14];
        xr[c] = v;
        ull v2 = pk2(v, v);
        const ulonglong2* wp = (const ulonglong2*)(w1t + c*32);
        #pragma unroll
        for (int i = 0; i < 8; i++) {
            ulonglong2 u = wp[i];
            fma2(h2[2*i],   v2, u.x, h2[2*i]);
            fma2(h2[2*i+1], v2, u.y, h2[2*i+1]);
        }
    }
    #pragma unroll
    for (int c = 0; c < 32; c++) {
        float v = x3b[c << 14];
        ull v2 = pk2(v, v);
        const ulonglong2* wp = (const ulonglong2*)(w1t + (32 + c)*32);
        #pragma unroll
        for (int i = 0; i < 8; i++) {
            ulonglong2 u = wp[i];
            fma2(h2[2*i],   v2, u.x, h2[2*i]);
            fma2(h2[2*i+1], v2, u.y, h2[2*i+1]);
        }
    }
    ull s01 = pk2(b2s[0], b2s[1]);
    #pragma unroll
    for (int i = 0; i < 16; i++) {
        float ha, hb; upk2(ha, hb, h2[i]);
        ha = fmaxf(ha, 0.f); hb = fmaxf(hb, 0.f);
        fma2(s01, pk2(ha, ha), w2p[2*i],   s01);
        fma2(s01, pk2(hb, hb), w2p[2*i+1], s01);
    }
    float s0, s1; upk2(s0, s1, s01);
    s0 = 1.f / (1.f + __expf(-s0));
    s1 = 1.f / (1.f + __expf(-s1));
    const float* yspb = ysps + b*32;
    const float* ychb = ychs + b*32;
    float* op = out + ((long)b << 19) + sp;
    #pragma unroll
    for (int c = 0; c < 32; c++) op[c << 14] = xr[c] + yspb[c]*s0 + ychb[c]*s1;
}

// ---------------- kernel 5: memory attention (per pixel-chunk, per head) ----------------
// Reads xo from out (its head's 8 channels), adds rec, writes back.
// Heads touch disjoint channels -> no race.
// mem stored in smem as slot-pairs: ps[(j*8+d)*2 + parity] = mem[2j+parity][d] * rs*log2e.
// Score computed directly in log2 domain (ex2, no pre-multiply, no horizontal add).
__global__ __launch_bounds__(256) void k_attn(
    const float* __restrict__ mem, float* __restrict__ out)
{
    __shared__ __align__(16) float ps[MSIZE*HD];  // 16KB
    int tid = threadIdx.x;
    int hd = blockIdx.y;
    const float RSL = 0.35355339059327373f * 1.4426950408889634f;  // rs*log2(e)

    const float* mh = mem + hd*MSIZE*HD;
    for (int i = tid; i < MSIZE*HD; i += 256) {
        int m = i >> 3, d = i & 7;
        ps[((m >> 1)*8 + d)*2 + (m & 1)] = mh[i] * RSL;
    }
    __syncthreads();

    int p = blockIdx.x * 256 + tid;
    int b = p >> 14, sp = p & 16383;
    float* base = out + ((long)b << 19) + ((long)hd*8 << 14) + sp;

    float qv[8];
    #pragma unroll
    for (int d = 0; d < 8; d++) qv[d] = base[d << 14];
    ull q2[8];
    #pragma unroll
    for (int d = 0; d < 8; d++) q2[d] = pk2(qv[d], qv[d]);

    ull r2[8], l2 = 0ULL;
    #pragma unroll
    for (int d = 0; d < 8; d++) r2[d] = 0ULL;

    const ulonglong2* pp = (const ulonglong2*)ps;
    #pragma unroll 8
    for (int j = 0; j < MSIZE/2; j++) {
        ulonglong2 u0 = pp[4*j + 0];   // (d0,d1) pairs
        ulonglong2 u1 = pp[4*j + 1];   // (d2,d3)
        ulonglong2 u2 = pp[4*j + 2];   // (d4,d5)
        ulonglong2 u3 = pp[4*j + 3];   // (d6,d7)
        ull s2;
        mul2(s2, q2[0], u0.x);
        fma2(s2, q2[1], u0.y, s2);
        fma2(s2, q2[2], u1.x, s2);
        fma2(s2, q2[3], u1.y, s2);
        fma2(s2, q2[4], u2.x, s2);
        fma2(s2, q2[5], u2.y, s2);
        fma2(s2, q2[6], u3.x, s2);
        fma2(s2, q2[7], u3.y, s2);
        float s0, s1; upk2(s0, s1, s2);
        ull e2 = pk2(ex2f(s0), ex2f(s1));
        add2(l2, l2, e2);
        fma2(r2[0], e2, u0.x, r2[0]);
        fma2(r2[1], e2, u0.y, r2[1]);
        fma2(r2[2], e2, u1.x, r2[2]);
        fma2(r2[3], e2, u1.y, r2[3]);
        fma2(r2[4], e2, u2.x, r2[4]);
        fma2(r2[5], e2, u2.y, r2[5]);
        fma2(r2[6], e2, u3.x, r2[6]);
        fma2(r2[7], e2, u3.y, r2[7]);
    }
    float ll, lh; upk2(ll, lh, l2);
    float inv = 1.f / ((ll + lh) * RSL);   // un-scale rec (msc = mem*RSL)
    #pragma unroll
    for (int d = 0; d < 8; d++) {
        float ra, rb; upk2(ra, rb, r2[d]);
        base[d << 14] = qv[d] + (ra + rb) * inv;
    }
}

extern "C" void kernel_launch(void* const* d_in, const int* in_sizes, int n_in,
                              void* d_out, int out_size) {
    const float* x     = (const float*)d_in[0];
    const float* fs_w1 = (const float*)d_in[1];
    const float* fs_w2 = (const float*)d_in[2];
    const float* fc_w1 = (const float*)d_in[3];
    const float* fc_w2 = (const float*)d_in[4];
    const float* sw_w1 = (const float*)d_in[5];
    const float* sw_b1 = (const float*)d_in[6];
    const float* sw_w2 = (const float*)d_in[7];
    const float* sw_b2 = (const float*)d_in[8];
    const float* off_w = (const float*)d_in[9];
    const float* off_b = (const float*)d_in[10];
    const float* dcn_w = (const float*)d_in[11];
    const float* dcn_b = (const float*)d_in[12];
    const float* mem   = (const float*)d_in[13];
    float* out = (float*)d_out;

    k_avg<<<Bq*Cc, 256>>>(x);
    k_mlp<<<1, 128>>>(fs_w1, fs_w2, fc_w1, fc_w2);
    k_off<<<BHW/256, 256>>>(x, off_w, off_b);
    k_dcn2<<<BHW/256, 256>>>(x, dcn_w, dcn_b);
    k_conv<<<BHW/256, 256>>>(x, sw_w1, sw_b1, sw_w2, sw_b2, out);
    dim3 ag(BHW/256, 4);
    k_attn<<<ag, 256>>>(mem, out);
}